// round 13
// baseline (speedup 1.0000x reference)
#include <cuda_runtime.h>
#include <cuda_bf16.h>

#define TT 512
#define BB 512
#define KK 8
#define VV 5
#define HH 30
#define NLL 4
#define NEL 8             // batch elements per CTA
#define NCTA (BB / NEL)   // 64 CTAs

__device__ float g_bufA[(size_t)TT * BB * HH];  // embed output (layer-0 input)
__device__ float g_bufB[(size_t)TT * BB * HH];  // final layer output (attn input)

// ---------- helpers ----------
__device__ __forceinline__ float tanh_ap(float x) {
    float r;
    asm("tanh.approx.f32 %0, %1;" : "=f"(r) : "f"(x));
    return r;
}
__device__ __forceinline__ float sigm_ap(float x) {
    return fmaf(0.5f, tanh_ap(0.5f * x), 0.5f);
}
__device__ __forceinline__ unsigned smem_u32(const void* p) {
    unsigned a;
    asm("{ .reg .u64 t; cvta.to.shared.u64 t, %1; cvt.u32.u64 %0, t; }"
        : "=r"(a) : "l"(p));
    return a;
}
__device__ __forceinline__ unsigned short bfbits(float v) {
    __nv_bfloat16 b = __float2bfloat16_rn(v);
    return *(unsigned short*)&b;
}
// mma.sync m16n8k16 bf16: D += A*B (D=C in-place)
__device__ __forceinline__ void mma16816(float* d, const unsigned* a,
                                         const unsigned* b) {
    asm volatile(
        "mma.sync.aligned.m16n8k16.row.col.f32.bf16.bf16.f32 "
        "{%0,%1,%2,%3},{%4,%5,%6,%7},{%8,%9},{%0,%1,%2,%3};"
        : "+f"(d[0]), "+f"(d[1]), "+f"(d[2]), "+f"(d[3])
        : "r"(a[0]), "r"(a[1]), "r"(a[2]), "r"(a[3]), "r"(b[0]), "r"(b[1]));
}
// ldmatrix x2 transposed (B-operand from [K][8] bf16 rows of 16B)
__device__ __forceinline__ void ldsm2t(unsigned* r, unsigned addr) {
    asm volatile(
        "ldmatrix.sync.aligned.m8n8.x2.trans.shared.b16 {%0,%1}, [%2];"
        : "=r"(r[0]), "=r"(r[1]) : "r"(addr));
}

// ---------- kernel 1: embedding + relu + mean over K (2 j per thread) ----------
__global__ void embed_kernel(const int* __restrict__ x,
                             const float* __restrict__ w,
                             const float* __restrict__ emb) {
    __shared__ float se[VV * HH];
    for (int i = threadIdx.x; i < VV * HH; i += blockDim.x) se[i] = emb[i];
    __syncthreads();
    int idx = blockIdx.x * blockDim.x + threadIdx.x;
    int p = idx % (HH / 2);
    size_t tb = (size_t)(idx / (HH / 2));
    const int* xp = x + tb * KK;
    const float* wp = w + tb * KK;
    float s0 = 0.f, s1 = 0.f;
#pragma unroll
    for (int k = 0; k < KK; k++) {
        int v = xp[k];
        float wk = wp[k];
        s0 += fmaxf(se[v * HH + 2 * p] * wk, 0.f);
        s1 += fmaxf(se[v * HH + 2 * p + 1] * wk, 0.f);
    }
    float2* outp = (float2*)(g_bufA + tb * HH + 2 * p);
    *outp = make_float2(s0 * (1.f / KK), s1 * (1.f / KK));
}

// ---------- kernel 2: 4 LSTM layers on mma.sync (HMMA bf16) ----------
// 64 CTAs x 256 threads (8 warps); CTA owns 8 batch elements.
// Per layer-step: gates(128x8) = W(128x61) . z, z = [x(30)|h(30)|1(bias)].
// W rows r = 4j+g. 3-term bf16 split: Whi*zhi + Whi*zlo + Wlo*zhi (f32 acc).
// Warp w owns m-tile w (rows 16w..16w+15 = units 4w..4w+3, all gates) for ALL
// 4 layers; weight fragments resident in registers (32 regs/layer/lane).
// z tiles in smem as [64 rows][8 cols] bf16 (16B rows), hi & lo planes, double
// buffered by t-parity; B-fragments via ldmatrix.x2.trans.
// Wavefront: layer l does t = s - l; one __syncthreads per wall-step.
__global__ void __launch_bounds__(256, 1)
lstm4_mma(const float* __restrict__ Wih_all, const float* __restrict__ Whh_all,
          const float* __restrict__ bih_all, const float* __restrict__ bhh_all) {
    __shared__ __align__(16) __nv_bfloat16 zt[NLL][2][2][64][8];  // [l][par][hi/lo][k][e]
    __shared__ __align__(16) float acts[8][NLL][16][8];

    const int tid = threadIdx.x;
    const int w = tid >> 5;
    const int ln = tid & 31;
    const int b0 = blockIdx.x * NEL;

    // ---- zero z tiles ----
    for (int i = tid; i < (int)(sizeof(zt) / 4); i += 256) ((unsigned*)zt)[i] = 0u;

    // ---- build resident A fragments (hi & lo) ----
    // reg i of frag(kt): row = 16w + (ln>>2) + (i&1)*8, cols cb,cb+1 with
    // cb = kt*16 + (ln&3)*2 + (i>>1)*8.
    unsigned Ah[NLL][4][4], Al[NLL][4][4];
#pragma unroll
    for (int l = 0; l < NLL; l++) {
        const float* Wih = Wih_all + l * 4 * HH * HH;
        const float* Whh = Whh_all + l * 4 * HH * HH;
        const float* bih = bih_all + l * 4 * HH;
        const float* bhh = bhh_all + l * 4 * HH;
#pragma unroll
        for (int kt = 0; kt < 4; kt++) {
#pragma unroll
            for (int i = 0; i < 4; i++) {
                int row = 16 * w + (ln >> 2) + (i & 1) * 8;
                int cb = kt * 16 + (ln & 3) * 2 + (i >> 1) * 8;
                float wv[2];
#pragma unroll
                for (int q = 0; q < 2; q++) {
                    int k = cb + q;
                    int j = row >> 2, g = row & 3;
                    float v = 0.f;
                    if (j < HH) {
                        int gr = g * HH + j;
                        if (k < HH) v = Wih[gr * HH + k];
                        else if (k < 2 * HH) v = Whh[gr * HH + (k - HH)];
                        else if (k == 60) v = bih[gr] + bhh[gr];
                    }
                    wv[q] = v;
                }
                unsigned short h0 = bfbits(wv[0]), h1 = bfbits(wv[1]);
                float r0 = wv[0] - __bfloat162float(*(__nv_bfloat16*)&h0);
                float r1 = wv[1] - __bfloat162float(*(__nv_bfloat16*)&h1);
                Ah[l][kt][i] = ((unsigned)h1 << 16) | h0;
                Al[l][kt][i] = ((unsigned)bfbits(r1) << 16) | bfbits(r0);
            }
        }
    }
    __syncthreads();  // zt zeroed before anyone writes below

    // ---- bias column: zhi[l][par][60][e] = 1.0 ----
    if (tid < NLL * 2 * NEL) {
        int l = tid >> 4, p = (tid >> 3) & 1, e = tid & 7;
        zt[l][p][0][60][e] = __float2bfloat16_rn(1.0f);
    }

    // ---- x staging roles: tid < 240 -> (el, k) ----
    const int xe = tid / HH, xk = tid - xe * HH;
    const bool xact = tid < NEL * HH;
    float xv = 0.f;
    if (xact) {
        float x0 = g_bufA[(size_t)(b0 + xe) * HH + xk];
        __nv_bfloat16 hh = __float2bfloat16_rn(x0);
        zt[0][0][0][xk][xe] = hh;
        zt[0][0][1][xk][xe] = __float2bfloat16_rn(x0 - __bfloat162float(hh));
        xv = g_bufA[((size_t)BB + b0 + xe) * HH + xk];
    }
    __syncthreads();

    const int uu = ln >> 3, ee = ln & 7;   // epilogue role: unit, element
    const int jg = 4 * w + uu;             // global unit
    float cst[NLL] = {0.f, 0.f, 0.f, 0.f};
    const unsigned rowsel = (unsigned)(ln & 15);

#pragma unroll 1
    for (int s = 0; s < TT + NLL - 1; s++) {
        float D[NLL][4];
        unsigned zb[NLL];
#pragma unroll
        for (int l = 0; l < NLL; l++) {
            D[l][0] = D[l][1] = D[l][2] = D[l][3] = 0.f;
            int t = s - l;
            zb[l] = smem_u32(&zt[l][t & 1][0][0][0]);
        }

        // ---- GEMM phase: all active layers ----
#pragma unroll
        for (int l = 0; l < NLL; l++) {
            int t = s - l;
            if (0 <= t && t < TT) {
                unsigned Bh[4][2], Bl[4][2];
#pragma unroll
                for (int kt = 0; kt < 4; kt++) {
                    unsigned ra = (unsigned)(kt * 16) + rowsel;
                    ldsm2t(Bh[kt], zb[l] + ra * 16u);
                    ldsm2t(Bl[kt], zb[l] + 1024u + ra * 16u);  // lo plane
                }
#pragma unroll
                for (int kt = 0; kt < 4; kt++) mma16816(D[l], Ah[l][kt], Bh[kt]);
#pragma unroll
                for (int kt = 0; kt < 4; kt++) mma16816(D[l], Ah[l][kt], Bl[kt]);
#pragma unroll
                for (int kt = 0; kt < 4; kt++) mma16816(D[l], Al[l][kt], Bh[kt]);
            }
        }

        // ---- x staging for layer 0, t = s+1; prefetch t = s+2 ----
        if (xact && s + 1 < TT) {
            int pn = (s + 1) & 1;
            __nv_bfloat16 hh = __float2bfloat16_rn(xv);
            zt[0][pn][0][xk][xe] = hh;
            zt[0][pn][1][xk][xe] = __float2bfloat16_rn(xv - __bfloat162float(hh));
            if (s + 2 < TT)
                xv = g_bufA[((size_t)(s + 2) * BB + b0 + xe) * HH + xk];
        }

        // ---- epilogue: D -> acts (warp-local exchange) ----
#pragma unroll
        for (int l = 0; l < NLL; l++) {
            int t = s - l;
            if (0 <= t && t < TT) {
                int r0 = ln >> 2, c0 = (ln & 3) * 2;
                *(float2*)&acts[w][l][r0][c0] = make_float2(D[l][0], D[l][1]);
                *(float2*)&acts[w][l][r0 + 8][c0] = make_float2(D[l][2], D[l][3]);
            }
        }
        __syncwarp();
#pragma unroll
        for (int l = 0; l < NLL; l++) {
            int t = s - l;
            if (0 <= t && t < TT) {
                float gi = acts[w][l][4 * uu + 0][ee];
                float gf = acts[w][l][4 * uu + 1][ee];
                float gg = acts[w][l][4 * uu + 2][ee];
                float go = acts[w][l][4 * uu + 3][ee];
                float i_ = sigm_ap(gi), f_ = sigm_ap(gf), o_ = sigm_ap(go);
                float g_ = tanh_ap(gg);
                float C = fmaf(f_, cst[l], i_ * g_);
                cst[l] = C;
                float h = o_ * tanh_ap(C);
                if (jg < HH) {
                    __nv_bfloat16 hh = __float2bfloat16_rn(h);
                    __nv_bfloat16 hl =
                        __float2bfloat16_rn(h - __bfloat162float(hh));
                    int pn = (t + 1) & 1;
                    zt[l][pn][0][HH + jg][ee] = hh;   // own-layer h for t+1
                    zt[l][pn][1][HH + jg][ee] = hl;
                    if (l < NLL - 1) {                // next layer's x for t
                        int pt = t & 1;
                        zt[l + 1][pt][0][jg][ee] = hh;
                        zt[l + 1][pt][1][jg][ee] = hl;
                    } else {
                        g_bufB[((size_t)t * BB + b0 + ee) * HH + jg] = h;
                    }
                }
            }
        }
        __syncthreads();
    }
}

// ---------- kernel 3: attention pooling + FC + softmax ----------
__global__ void __launch_bounds__(256)
attn_kernel(const float* __restrict__ W1, const float* __restrict__ b1,
            const float* __restrict__ W2, const float* __restrict__ b2,
            const float* __restrict__ fcW, const float* __restrict__ fcb,
            float* __restrict__ outp) {
    const float* __restrict__ enc = g_bufB;
    const int b = blockIdx.x, tid = threadIdx.x;

    __shared__ float4 sW1[HH * 16];
    __shared__ float4 sB1[16];
    __shared__ float4 sW2[16];
    __shared__ float se[TT];
    __shared__ float sred[8];
    __shared__ float swsum[8][HH];
    __shared__ float spool[HH];
    __shared__ float sscal[2];

    for (int i = tid; i < HH * 16; i += 256) sW1[i] = ((const float4*)W1)[i];
    if (tid < 16) {
        sB1[tid] = ((const float4*)b1)[tid];
        sW2[tid] = ((const float4*)W2)[tid];
    }
    __syncthreads();

    const float b2v = b2[0];
    for (int tt = tid; tt < TT; tt += 256) {
        const float* hp = enc + ((size_t)tt * BB + b) * HH;
        float4 acc[16];
#pragma unroll
        for (int q = 0; q < 16; q++) acc[q] = sB1[q];
        for (int jj = 0; jj < HH; jj++) {
            float hj = __ldg(hp + jj);
#pragma unroll
            for (int q = 0; q < 16; q++) {
                float4 wv = sW1[jj * 16 + q];
                acc[q].x = fmaf(hj, wv.x, acc[q].x);
                acc[q].y = fmaf(hj, wv.y, acc[q].y);
                acc[q].z = fmaf(hj, wv.z, acc[q].z);
                acc[q].w = fmaf(hj, wv.w, acc[q].w);
            }
        }
        float e = b2v;
#pragma unroll
        for (int q = 0; q < 16; q++) {
            float4 w2 = sW2[q];
            e += fmaxf(acc[q].x, 0.f) * w2.x + fmaxf(acc[q].y, 0.f) * w2.y +
                 fmaxf(acc[q].z, 0.f) * w2.z + fmaxf(acc[q].w, 0.f) * w2.w;
        }
        se[tt] = e;
    }
    __syncthreads();

    float m = -1e30f;
    for (int i = tid; i < TT; i += 256) m = fmaxf(m, se[i]);
#pragma unroll
    for (int o = 16; o; o >>= 1) m = fmaxf(m, __shfl_xor_sync(0xffffffffu, m, o));
    if ((tid & 31) == 0) sred[tid >> 5] = m;
    __syncthreads();
    if (tid < 32) {
        float v = (tid < 8) ? sred[tid] : -1e30f;
#pragma unroll
        for (int o = 4; o; o >>= 1) v = fmaxf(v, __shfl_xor_sync(0xffffffffu, v, o));
        if (tid == 0) sscal[0] = v;
    }
    __syncthreads();
    const float M = sscal[0];
    float ssum = 0.f;
    for (int i = tid; i < TT; i += 256) {
        float e = __expf(se[i] - M);
        se[i] = e;
        ssum += e;
    }
#pragma unroll
    for (int o = 16; o; o >>= 1) ssum += __shfl_xor_sync(0xffffffffu, ssum, o);
    if ((tid & 31) == 0) sred[tid >> 5] = ssum;
    __syncthreads();
    if (tid < 32) {
        float v = (tid < 8) ? sred[tid] : 0.f;
#pragma unroll
        for (int o = 4; o; o >>= 1) v += __shfl_xor_sync(0xffffffffu, v, o);
        if (tid == 0) sscal[1] = __fdividef(1.f, v);
    }
    __syncthreads();
    const float inv = sscal[1];

    float pa[HH];
#pragma unroll
    for (int jj = 0; jj < HH; jj++) pa[jj] = 0.f;
    for (int tt = tid; tt < TT; tt += 256) {
        float wgt = se[tt] * inv;
        const float* hp = enc + ((size_t)tt * BB + b) * HH;
#pragma unroll
        for (int jj = 0; jj < HH; jj++) pa[jj] = fmaf(wgt, __ldg(hp + jj), pa[jj]);
    }
#pragma unroll
    for (int jj = 0; jj < HH; jj++) {
#pragma unroll
        for (int o = 16; o; o >>= 1) pa[jj] += __shfl_xor_sync(0xffffffffu, pa[jj], o);
    }
    if ((tid & 31) == 0) {
        int w = tid >> 5;
#pragma unroll
        for (int jj = 0; jj < HH; jj++) swsum[w][jj] = pa[jj];
    }
    __syncthreads();
    if (tid < HH) {
        float s = 0.f;
#pragma unroll
        for (int w = 0; w < 8; w++) s += swsum[w][tid];
        spool[tid] = s;
    }
    __syncthreads();
    if (tid == 0) {
        float l0 = fcb[0], l1 = fcb[1], l2 = fcb[2];
#pragma unroll
        for (int jj = 0; jj < HH; jj++) {
            float p = spool[jj];
            l0 = fmaf(p, fcW[jj * 3 + 0], l0);
            l1 = fmaf(p, fcW[jj * 3 + 1], l1);
            l2 = fmaf(p, fcW[jj * 3 + 2], l2);
        }
        float mx = fmaxf(l0, fmaxf(l1, l2));
        float e0 = __expf(l0 - mx), e1 = __expf(l1 - mx), e2 = __expf(l2 - mx);
        float is = __fdividef(1.f, e0 + e1 + e2);
        outp[b * 3 + 0] = e0 * is;
        outp[b * 3 + 1] = e1 * is;
        outp[b * 3 + 2] = e2 * is;
    }
}

// ---------- launch ----------
extern "C" void kernel_launch(void* const* d_in, const int* in_sizes, int n_in,
                              void* d_out, int out_size) {
    const int*   x   = (const int*)  d_in[0];
    const float* wx  = (const float*)d_in[1];
    const float* emb = (const float*)d_in[2];
    const float* Wih = (const float*)d_in[3];
    const float* Whh = (const float*)d_in[4];
    const float* bih = (const float*)d_in[5];
    const float* bhh = (const float*)d_in[6];
    const float* aW1 = (const float*)d_in[7];
    const float* ab1 = (const float*)d_in[8];
    const float* aW2 = (const float*)d_in[9];
    const float* ab2 = (const float*)d_in[10];
    const float* fcW = (const float*)d_in[11];
    const float* fcb = (const float*)d_in[12];
    float* outp = (float*)d_out;

    embed_kernel<<<(TT * BB * (HH / 2)) / 256, 256>>>(x, wx, emb);
    lstm4_mma<<<NCTA, 256>>>(Wih, Whh, bih, bhh);
    attn_kernel<<<BB, 256>>>(aW1, ab1, aW2, ab2, fcW, fcb, outp);
}

// round 14
// speedup vs baseline: 1.1397x; 1.1397x over previous
#include <cuda_runtime.h>
#include <cuda_bf16.h>

#define TT 512
#define BB 512
#define KK 8
#define VV 5
#define HH 30
#define NLL 4
#define NEL 8             // batch elements per CTA
#define NCTA (BB / NEL)   // 64 CTAs

__device__ float g_bufA[(size_t)TT * BB * HH];  // embed output (layer-0 input)
__device__ float g_bufB[(size_t)TT * BB * HH];  // final layer output (attn input)

// ---------- helpers ----------
__device__ __forceinline__ float tanh_ap(float x) {
    float r;
    asm("tanh.approx.f32 %0, %1;" : "=f"(r) : "f"(x));
    return r;
}
__device__ __forceinline__ float sigm_ap(float x) {
    return fmaf(0.5f, tanh_ap(0.5f * x), 0.5f);
}
__device__ __forceinline__ unsigned smem_u32(const void* p) {
    unsigned a;
    asm("{ .reg .u64 t; cvta.to.shared.u64 t, %1; cvt.u32.u64 %0, t; }"
        : "=r"(a) : "l"(p));
    return a;
}
__device__ __forceinline__ unsigned short bfbits(float v) {
    __nv_bfloat16 b = __float2bfloat16_rn(v);
    return *(unsigned short*)&b;
}
// mma.sync m16n8k16 bf16: D += A*B (D=C in-place)
__device__ __forceinline__ void mma16816(float* d, const unsigned* a,
                                         const unsigned* b) {
    asm volatile(
        "mma.sync.aligned.m16n8k16.row.col.f32.bf16.bf16.f32 "
        "{%0,%1,%2,%3},{%4,%5,%6,%7},{%8,%9},{%0,%1,%2,%3};"
        : "+f"(d[0]), "+f"(d[1]), "+f"(d[2]), "+f"(d[3])
        : "r"(a[0]), "r"(a[1]), "r"(a[2]), "r"(a[3]), "r"(b[0]), "r"(b[1]));
}
// ldmatrix x2 transposed (B-operand from [K][8] bf16 rows of 16B)
__device__ __forceinline__ void ldsm2t(unsigned* r, unsigned addr) {
    asm volatile(
        "ldmatrix.sync.aligned.m8n8.x2.trans.shared.b16 {%0,%1}, [%2];"
        : "=r"(r[0]), "=r"(r[1]) : "r"(addr));
}

// ---------- kernel 1: embedding + relu + mean over K (2 j per thread) ----------
__global__ void embed_kernel(const int* __restrict__ x,
                             const float* __restrict__ w,
                             const float* __restrict__ emb) {
    __shared__ float se[VV * HH];
    for (int i = threadIdx.x; i < VV * HH; i += blockDim.x) se[i] = emb[i];
    __syncthreads();
    int idx = blockIdx.x * blockDim.x + threadIdx.x;
    int p = idx % (HH / 2);
    size_t tb = (size_t)(idx / (HH / 2));
    const int* xp = x + tb * KK;
    const float* wp = w + tb * KK;
    float s0 = 0.f, s1 = 0.f;
#pragma unroll
    for (int k = 0; k < KK; k++) {
        int v = xp[k];
        float wk = wp[k];
        s0 += fmaxf(se[v * HH + 2 * p] * wk, 0.f);
        s1 += fmaxf(se[v * HH + 2 * p + 1] * wk, 0.f);
    }
    float2* outp = (float2*)(g_bufA + tb * HH + 2 * p);
    *outp = make_float2(s0 * (1.f / KK), s1 * (1.f / KK));
}

// ---------- kernel 2: 4 LSTM layers on mma.sync (HMMA bf16) ----------
// 64 CTAs x 256 threads (8 warps); CTA owns 8 batch elements.
// gates(128x8) = W(128x61) . z, z = [x(30)|h(30)|1(bias)], 3-term bf16 split.
// Warp w owns m-tile w (units 4w..4w+3, all gates) for all layers; A fragments
// resident in registers. THREE independent accumulator chains per layer (one
// per split term, depth 4 each) + branch-free steady-state loop so ptxas can
// keep all 12 chains of a warp in flight (R13 had one guarded 12-deep chain
// per layer -> exposed HMMA latency dominated the step).
__global__ void __launch_bounds__(256, 1)
lstm4_mma(const float* __restrict__ Wih_all, const float* __restrict__ Whh_all,
          const float* __restrict__ bih_all, const float* __restrict__ bhh_all) {
    __shared__ __align__(16) __nv_bfloat16 zt[NLL][2][2][64][8];  // [l][par][hi/lo][k][e]
    __shared__ __align__(16) float acts[8][NLL][16][8];

    const int tid = threadIdx.x;
    const int w = tid >> 5;
    const int ln = tid & 31;
    const int b0 = blockIdx.x * NEL;

    for (int i = tid; i < (int)(sizeof(zt) / 4); i += 256) ((unsigned*)zt)[i] = 0u;

    // ---- resident A fragments (hi & lo) ----
    unsigned Ah[NLL][4][4], Al[NLL][4][4];
#pragma unroll
    for (int l = 0; l < NLL; l++) {
        const float* Wih = Wih_all + l * 4 * HH * HH;
        const float* Whh = Whh_all + l * 4 * HH * HH;
        const float* bih = bih_all + l * 4 * HH;
        const float* bhh = bhh_all + l * 4 * HH;
#pragma unroll
        for (int kt = 0; kt < 4; kt++) {
#pragma unroll
            for (int i = 0; i < 4; i++) {
                int row = 16 * w + (ln >> 2) + (i & 1) * 8;
                int cb = kt * 16 + (ln & 3) * 2 + (i >> 1) * 8;
                float wv[2];
#pragma unroll
                for (int q = 0; q < 2; q++) {
                    int k = cb + q;
                    int j = row >> 2, g = row & 3;
                    float v = 0.f;
                    if (j < HH) {
                        int gr = g * HH + j;
                        if (k < HH) v = Wih[gr * HH + k];
                        else if (k < 2 * HH) v = Whh[gr * HH + (k - HH)];
                        else if (k == 60) v = bih[gr] + bhh[gr];
                    }
                    wv[q] = v;
                }
                unsigned short h0 = bfbits(wv[0]), h1 = bfbits(wv[1]);
                float r0 = wv[0] - __bfloat162float(*(__nv_bfloat16*)&h0);
                float r1 = wv[1] - __bfloat162float(*(__nv_bfloat16*)&h1);
                Ah[l][kt][i] = ((unsigned)h1 << 16) | h0;
                Al[l][kt][i] = ((unsigned)bfbits(r1) << 16) | bfbits(r0);
            }
        }
    }
    __syncthreads();

    // ---- bias column ----
    if (tid < NLL * 2 * NEL) {
        int l = tid >> 4, p = (tid >> 3) & 1, e = tid & 7;
        zt[l][p][0][60][e] = __float2bfloat16_rn(1.0f);
    }

    // ---- x staging roles ----
    const int xe = tid / HH, xk = tid - xe * HH;
    const bool xact = tid < NEL * HH;
    float xv = 0.f;
    if (xact) {
        float x0 = g_bufA[(size_t)(b0 + xe) * HH + xk];
        __nv_bfloat16 hh = __float2bfloat16_rn(x0);
        zt[0][0][0][xk][xe] = hh;
        zt[0][0][1][xk][xe] = __float2bfloat16_rn(x0 - __bfloat162float(hh));
        xv = g_bufA[((size_t)BB + b0 + xe) * HH + xk];
    }
    __syncthreads();

    const int uu = ln >> 3, ee = ln & 7;
    const int jg = 4 * w + uu;
    float cst[NLL] = {0.f, 0.f, 0.f, 0.f};
    const unsigned rowsel = (unsigned)(ln & 15);

// PRED(l,t): compile-time 1 in steady state, range check on the fringe.
#define STEP_BODY(PRED)                                                        \
    {                                                                          \
        unsigned Bh[4][2], Bl[4][2];                                           \
        float D0[NLL][4], D1[NLL][4], D2[NLL][4];                              \
        _Pragma("unroll")                                                      \
        for (int l = 0; l < NLL; l++) {                                        \
            const int t = s - l;                                               \
            _Pragma("unroll")                                                  \
            for (int i = 0; i < 4; i++)                                        \
                D0[l][i] = D1[l][i] = D2[l][i] = 0.f;                          \
            if (PRED) {                                                        \
                const unsigned zb = smem_u32(&zt[l][t & 1][0][0][0]);          \
                _Pragma("unroll")                                              \
                for (int kt = 0; kt < 4; kt++) {                               \
                    unsigned ra = (unsigned)(kt * 16) + rowsel;                \
                    ldsm2t(Bh[kt], zb + ra * 16u);                             \
                    ldsm2t(Bl[kt], zb + 1024u + ra * 16u);                     \
                }                                                              \
                _Pragma("unroll")                                              \
                for (int kt = 0; kt < 4; kt++) {                               \
                    mma16816(D0[l], Ah[l][kt], Bh[kt]);                        \
                    mma16816(D1[l], Ah[l][kt], Bl[kt]);                        \
                    mma16816(D2[l], Al[l][kt], Bh[kt]);                        \
                }                                                              \
            }                                                                  \
        }                                                                      \
        if (xact && s + 1 < TT) {                                              \
            int pn = (s + 1) & 1;                                              \
            __nv_bfloat16 hh = __float2bfloat16_rn(xv);                        \
            zt[0][pn][0][xk][xe] = hh;                                         \
            zt[0][pn][1][xk][xe] =                                             \
                __float2bfloat16_rn(xv - __bfloat162float(hh));                \
            if (s + 2 < TT)                                                    \
                xv = g_bufA[((size_t)(s + 2) * BB + b0 + xe) * HH + xk];       \
        }                                                                      \
        _Pragma("unroll")                                                      \
        for (int l = 0; l < NLL; l++) {                                        \
            const int t = s - l;                                               \
            if (PRED) {                                                        \
                int r0 = ln >> 2, c0 = (ln & 3) * 2;                           \
                *(float2*)&acts[w][l][r0][c0] =                                \
                    make_float2(D0[l][0] + D1[l][0] + D2[l][0],                \
                                D0[l][1] + D1[l][1] + D2[l][1]);               \
                *(float2*)&acts[w][l][r0 + 8][c0] =                            \
                    make_float2(D0[l][2] + D1[l][2] + D2[l][2],                \
                                D0[l][3] + D1[l][3] + D2[l][3]);               \
            }                                                                  \
        }                                                                      \
        __syncwarp();                                                          \
        _Pragma("unroll")                                                      \
        for (int l = 0; l < NLL; l++) {                                        \
            const int t = s - l;                                               \
            if (PRED) {                                                        \
                float gi = acts[w][l][4 * uu + 0][ee];                         \
                float gf = acts[w][l][4 * uu + 1][ee];                         \
                float gg = acts[w][l][4 * uu + 2][ee];                         \
                float go = acts[w][l][4 * uu + 3][ee];                         \
                float i_ = sigm_ap(gi), f_ = sigm_ap(gf), o_ = sigm_ap(go);    \
                float g_ = tanh_ap(gg);                                        \
                float C = fmaf(f_, cst[l], i_ * g_);                           \
                cst[l] = C;                                                    \
                float h = o_ * tanh_ap(C);                                     \
                if (jg < HH) {                                                 \
                    __nv_bfloat16 hh = __float2bfloat16_rn(h);                 \
                    __nv_bfloat16 hl =                                         \
                        __float2bfloat16_rn(h - __bfloat162float(hh));         \
                    int pn = (t + 1) & 1;                                      \
                    zt[l][pn][0][HH + jg][ee] = hh;                            \
                    zt[l][pn][1][HH + jg][ee] = hl;                            \
                    if (l < NLL - 1) {                                         \
                        int pt = t & 1;                                        \
                        zt[l + 1][pt][0][jg][ee] = hh;                         \
                        zt[l + 1][pt][1][jg][ee] = hl;                         \
                    } else {                                                   \
                        g_bufB[((size_t)t * BB + b0 + ee) * HH + jg] = h;      \
                    }                                                          \
                }                                                              \
            }                                                                  \
        }                                                                      \
        __syncthreads();                                                       \
    }

    // fringe-in: s = 0..2 (guarded)
#pragma unroll 1
    for (int s = 0; s < NLL - 1; s++) STEP_BODY(0 <= t && t < TT)
    // steady state: all 4 layers unconditionally active (branch-free GEMM)
#pragma unroll 1
    for (int s = NLL - 1; s < TT; s++) STEP_BODY(1)
    // fringe-out: s = TT..TT+2 (guarded)
#pragma unroll 1
    for (int s = TT; s < TT + NLL - 1; s++) STEP_BODY(0 <= t && t < TT)
#undef STEP_BODY
}

// ---------- kernel 3: attention pooling + FC + softmax ----------
__global__ void __launch_bounds__(256)
attn_kernel(const float* __restrict__ W1, const float* __restrict__ b1,
            const float* __restrict__ W2, const float* __restrict__ b2,
            const float* __restrict__ fcW, const float* __restrict__ fcb,
            float* __restrict__ outp) {
    const float* __restrict__ enc = g_bufB;
    const int b = blockIdx.x, tid = threadIdx.x;

    __shared__ float4 sW1[HH * 16];
    __shared__ float4 sB1[16];
    __shared__ float4 sW2[16];
    __shared__ float se[TT];
    __shared__ float sred[8];
    __shared__ float swsum[8][HH];
    __shared__ float spool[HH];
    __shared__ float sscal[2];

    for (int i = tid; i < HH * 16; i += 256) sW1[i] = ((const float4*)W1)[i];
    if (tid < 16) {
        sB1[tid] = ((const float4*)b1)[tid];
        sW2[tid] = ((const float4*)W2)[tid];
    }
    __syncthreads();

    const float b2v = b2[0];
    for (int tt = tid; tt < TT; tt += 256) {
        const float* hp = enc + ((size_t)tt * BB + b) * HH;
        float4 acc[16];
#pragma unroll
        for (int q = 0; q < 16; q++) acc[q] = sB1[q];
        for (int jj = 0; jj < HH; jj++) {
            float hj = __ldg(hp + jj);
#pragma unroll
            for (int q = 0; q < 16; q++) {
                float4 wv = sW1[jj * 16 + q];
                acc[q].x = fmaf(hj, wv.x, acc[q].x);
                acc[q].y = fmaf(hj, wv.y, acc[q].y);
                acc[q].z = fmaf(hj, wv.z, acc[q].z);
                acc[q].w = fmaf(hj, wv.w, acc[q].w);
            }
        }
        float e = b2v;
#pragma unroll
        for (int q = 0; q < 16; q++) {
            float4 w2 = sW2[q];
            e += fmaxf(acc[q].x, 0.f) * w2.x + fmaxf(acc[q].y, 0.f) * w2.y +
                 fmaxf(acc[q].z, 0.f) * w2.z + fmaxf(acc[q].w, 0.f) * w2.w;
        }
        se[tt] = e;
    }
    __syncthreads();

    float m = -1e30f;
    for (int i = tid; i < TT; i += 256) m = fmaxf(m, se[i]);
#pragma unroll
    for (int o = 16; o; o >>= 1) m = fmaxf(m, __shfl_xor_sync(0xffffffffu, m, o));
    if ((tid & 31) == 0) sred[tid >> 5] = m;
    __syncthreads();
    if (tid < 32) {
        float v = (tid < 8) ? sred[tid] : -1e30f;
#pragma unroll
        for (int o = 4; o; o >>= 1) v = fmaxf(v, __shfl_xor_sync(0xffffffffu, v, o));
        if (tid == 0) sscal[0] = v;
    }
    __syncthreads();
    const float M = sscal[0];
    float ssum = 0.f;
    for (int i = tid; i < TT; i += 256) {
        float e = __expf(se[i] - M);
        se[i] = e;
        ssum += e;
    }
#pragma unroll
    for (int o = 16; o; o >>= 1) ssum += __shfl_xor_sync(0xffffffffu, ssum, o);
    if ((tid & 31) == 0) sred[tid >> 5] = ssum;
    __syncthreads();
    if (tid < 32) {
        float v = (tid < 8) ? sred[tid] : 0.f;
#pragma unroll
        for (int o = 4; o; o >>= 1) v += __shfl_xor_sync(0xffffffffu, v, o);
        if (tid == 0) sscal[1] = __fdividef(1.f, v);
    }
    __syncthreads();
    const float inv = sscal[1];

    float pa[HH];
#pragma unroll
    for (int jj = 0; jj < HH; jj++) pa[jj] = 0.f;
    for (int tt = tid; tt < TT; tt += 256) {
        float wgt = se[tt] * inv;
        const float* hp = enc + ((size_t)tt * BB + b) * HH;
#pragma unroll
        for (int jj = 0; jj < HH; jj++) pa[jj] = fmaf(wgt, __ldg(hp + jj), pa[jj]);
    }
#pragma unroll
    for (int jj = 0; jj < HH; jj++) {
#pragma unroll
        for (int o = 16; o; o >>= 1) pa[jj] += __shfl_xor_sync(0xffffffffu, pa[jj], o);
    }
    if ((tid & 31) == 0) {
        int w = tid >> 5;
#pragma unroll
        for (int jj = 0; jj < HH; jj++) swsum[w][jj] = pa[jj];
    }
    __syncthreads();
    if (tid < HH) {
        float s = 0.f;
#pragma unroll
        for (int w = 0; w < 8; w++) s += swsum[w][tid];
        spool[tid] = s;
    }
    __syncthreads();
    if (tid == 0) {
        float l0 = fcb[0], l1 = fcb[1], l2 = fcb[2];
#pragma unroll
        for (int jj = 0; jj < HH; jj++) {
            float p = spool[jj];
            l0 = fmaf(p, fcW[jj * 3 + 0], l0);
            l1 = fmaf(p, fcW[jj * 3 + 1], l1);
            l2 = fmaf(p, fcW[jj * 3 + 2], l2);
        }
        float mx = fmaxf(l0, fmaxf(l1, l2));
        float e0 = __expf(l0 - mx), e1 = __expf(l1 - mx), e2 = __expf(l2 - mx);
        float is = __fdividef(1.f, e0 + e1 + e2);
        outp[b * 3 + 0] = e0 * is;
        outp[b * 3 + 1] = e1 * is;
        outp[b * 3 + 2] = e2 * is;
    }
}

// ---------- launch ----------
extern "C" void kernel_launch(void* const* d_in, const int* in_sizes, int n_in,
                              void* d_out, int out_size) {
    const int*   x   = (const int*)  d_in[0];
    const float* wx  = (const float*)d_in[1];
    const float* emb = (const float*)d_in[2];
    const float* Wih = (const float*)d_in[3];
    const float* Whh = (const float*)d_in[4];
    const float* bih = (const float*)d_in[5];
    const float* bhh = (const float*)d_in[6];
    const float* aW1 = (const float*)d_in[7];
    const float* ab1 = (const float*)d_in[8];
    const float* aW2 = (const float*)d_in[9];
    const float* ab2 = (const float*)d_in[10];
    const float* fcW = (const float*)d_in[11];
    const float* fcb = (const float*)d_in[12];
    float* outp = (float*)d_out;

    embed_kernel<<<(TT * BB * (HH / 2)) / 256, 256>>>(x, wx, emb);
    lstm4_mma<<<NCTA, 256>>>(Wih, Whh, bih, bhh);
    attn_kernel<<<BB, 256>>>(aW1, ab1, aW2, ab2, fcW, fcb, outp);
}

// round 15
// speedup vs baseline: 1.2197x; 1.0703x over previous
#include <cuda_runtime.h>
#include <cuda_bf16.h>

#define TT 512
#define BB 512
#define KK 8
#define VV 5
#define HH 30
#define NLL 4
#define NEL 8             // batch elements per CTA
#define NCTA (BB / NEL)   // 64 CTAs

__device__ float g_bufA[(size_t)TT * BB * HH];  // embed output (layer-0 input)
__device__ float g_bufB[(size_t)TT * BB * HH];  // final layer output (attn input)

// ---------- helpers ----------
__device__ __forceinline__ float tanh_ap(float x) {
    float r;
    asm("tanh.approx.f32 %0, %1;" : "=f"(r) : "f"(x));
    return r;
}
__device__ __forceinline__ float sigm_ap(float x) {
    return fmaf(0.5f, tanh_ap(0.5f * x), 0.5f);
}
__device__ __forceinline__ unsigned smem_u32(const void* p) {
    unsigned a;
    asm("{ .reg .u64 t; cvta.to.shared.u64 t, %1; cvt.u32.u64 %0, t; }"
        : "=r"(a) : "l"(p));
    return a;
}
__device__ __forceinline__ unsigned short bfbits(float v) {
    __nv_bfloat16 b = __float2bfloat16_rn(v);
    return *(unsigned short*)&b;
}
// mma.sync m16n8k16 bf16: D += A*B (D=C in-place)
__device__ __forceinline__ void mma16816(float* d, const unsigned* a,
                                         const unsigned* b) {
    asm volatile(
        "mma.sync.aligned.m16n8k16.row.col.f32.bf16.bf16.f32 "
        "{%0,%1,%2,%3},{%4,%5,%6,%7},{%8,%9},{%0,%1,%2,%3};"
        : "+f"(d[0]), "+f"(d[1]), "+f"(d[2]), "+f"(d[3])
        : "r"(a[0]), "r"(a[1]), "r"(a[2]), "r"(a[3]), "r"(b[0]), "r"(b[1]));
}
// ldmatrix x2 transposed (B-operand from [K][8] bf16 rows of 16B)
__device__ __forceinline__ void ldsm2t(unsigned* r, unsigned addr) {
    asm volatile(
        "ldmatrix.sync.aligned.m8n8.x2.trans.shared.b16 {%0,%1}, [%2];"
        : "=r"(r[0]), "=r"(r[1]) : "r"(addr));
}

// ---------- kernel 1: embedding + relu + mean over K (2 j per thread) ----------
__global__ void embed_kernel(const int* __restrict__ x,
                             const float* __restrict__ w,
                             const float* __restrict__ emb) {
    __shared__ float se[VV * HH];
    for (int i = threadIdx.x; i < VV * HH; i += blockDim.x) se[i] = emb[i];
    __syncthreads();
    int idx = blockIdx.x * blockDim.x + threadIdx.x;
    int p = idx % (HH / 2);
    size_t tb = (size_t)(idx / (HH / 2));
    const int* xp = x + tb * KK;
    const float* wp = w + tb * KK;
    float s0 = 0.f, s1 = 0.f;
#pragma unroll
    for (int k = 0; k < KK; k++) {
        int v = xp[k];
        float wk = wp[k];
        s0 += fmaxf(se[v * HH + 2 * p] * wk, 0.f);
        s1 += fmaxf(se[v * HH + 2 * p + 1] * wk, 0.f);
    }
    float2* outp = (float2*)(g_bufA + tb * HH + 2 * p);
    *outp = make_float2(s0 * (1.f / KK), s1 * (1.f / KK));
}

// ---------- kernel 2: 4 LSTM layers on mma.sync (HMMA bf16) ----------
// 64 CTAs x 256 threads (8 warps); CTA owns 8 batch elements.
// gates(128x8) = W(128x61) . z, z = [x(30)|h(30)|1(bias)].
// 2-term split: Whi*zhi + Whi*zlo (z kept hi/lo to cover input rounding;
// weight residual term dropped -> -4 MMA/step, -80 regs vs R14).
// Warp w owns m-tile w (units 4w..4w+3, all gates) for all layers; A fragments
// resident in registers; 2 independent accumulator chains per layer.
__global__ void __launch_bounds__(256, 1)
lstm4_mma(const float* __restrict__ Wih_all, const float* __restrict__ Whh_all,
          const float* __restrict__ bih_all, const float* __restrict__ bhh_all) {
    __shared__ __align__(16) __nv_bfloat16 zt[NLL][2][2][64][8];  // [l][par][hi/lo][k][e]
    __shared__ __align__(16) float acts[8][NLL][16][8];

    const int tid = threadIdx.x;
    const int w = tid >> 5;
    const int ln = tid & 31;
    const int b0 = blockIdx.x * NEL;

    for (int i = tid; i < (int)(sizeof(zt) / 4); i += 256) ((unsigned*)zt)[i] = 0u;

    // ---- resident A fragments (hi only) ----
    unsigned Ah[NLL][4][4];
#pragma unroll
    for (int l = 0; l < NLL; l++) {
        const float* Wih = Wih_all + l * 4 * HH * HH;
        const float* Whh = Whh_all + l * 4 * HH * HH;
        const float* bih = bih_all + l * 4 * HH;
        const float* bhh = bhh_all + l * 4 * HH;
#pragma unroll
        for (int kt = 0; kt < 4; kt++) {
#pragma unroll
            for (int i = 0; i < 4; i++) {
                int row = 16 * w + (ln >> 2) + (i & 1) * 8;
                int cb = kt * 16 + (ln & 3) * 2 + (i >> 1) * 8;
                float wv[2];
#pragma unroll
                for (int q = 0; q < 2; q++) {
                    int k = cb + q;
                    int j = row >> 2, g = row & 3;
                    float v = 0.f;
                    if (j < HH) {
                        int gr = g * HH + j;
                        if (k < HH) v = Wih[gr * HH + k];
                        else if (k < 2 * HH) v = Whh[gr * HH + (k - HH)];
                        else if (k == 60) v = bih[gr] + bhh[gr];
                    }
                    wv[q] = v;
                }
                unsigned short h0 = bfbits(wv[0]), h1 = bfbits(wv[1]);
                Ah[l][kt][i] = ((unsigned)h1 << 16) | h0;
            }
        }
    }
    __syncthreads();

    // ---- bias column ----
    if (tid < NLL * 2 * NEL) {
        int l = tid >> 4, p = (tid >> 3) & 1, e = tid & 7;
        zt[l][p][0][60][e] = __float2bfloat16_rn(1.0f);
    }

    // ---- x staging roles ----
    const int xe = tid / HH, xk = tid - xe * HH;
    const bool xact = tid < NEL * HH;
    float xv = 0.f;
    if (xact) {
        float x0 = g_bufA[(size_t)(b0 + xe) * HH + xk];
        __nv_bfloat16 hh = __float2bfloat16_rn(x0);
        zt[0][0][0][xk][xe] = hh;
        zt[0][0][1][xk][xe] = __float2bfloat16_rn(x0 - __bfloat162float(hh));
        xv = g_bufA[((size_t)BB + b0 + xe) * HH + xk];
    }
    __syncthreads();

    const int uu = ln >> 3, ee = ln & 7;
    const int jg = 4 * w + uu;
    float cst[NLL] = {0.f, 0.f, 0.f, 0.f};
    const unsigned rowsel = (unsigned)(ln & 15);

// PRED(l,t): compile-time 1 in steady state, range check on the fringe.
#define STEP_BODY(PRED)                                                        \
    {                                                                          \
        unsigned Bh[4][2], Bl[4][2];                                           \
        float D0[NLL][4], D1[NLL][4];                                          \
        _Pragma("unroll")                                                      \
        for (int l = 0; l < NLL; l++) {                                        \
            const int t = s - l;                                               \
            _Pragma("unroll")                                                  \
            for (int i = 0; i < 4; i++) D0[l][i] = D1[l][i] = 0.f;             \
            if (PRED) {                                                        \
                const unsigned zb = smem_u32(&zt[l][t & 1][0][0][0]);          \
                _Pragma("unroll")                                              \
                for (int kt = 0; kt < 4; kt++) {                               \
                    unsigned ra = (unsigned)(kt * 16) + rowsel;                \
                    ldsm2t(Bh[kt], zb + ra * 16u);                             \
                    ldsm2t(Bl[kt], zb + 1024u + ra * 16u);                     \
                }                                                              \
                _Pragma("unroll")                                              \
                for (int kt = 0; kt < 4; kt++) {                               \
                    mma16816(D0[l], Ah[l][kt], Bh[kt]);                        \
                    mma16816(D1[l], Ah[l][kt], Bl[kt]);                        \
                }                                                              \
            }                                                                  \
        }                                                                      \
        if (xact && s + 1 < TT) {                                              \
            int pn = (s + 1) & 1;                                              \
            __nv_bfloat16 hh = __float2bfloat16_rn(xv);                        \
            zt[0][pn][0][xk][xe] = hh;                                         \
            zt[0][pn][1][xk][xe] =                                             \
                __float2bfloat16_rn(xv - __bfloat162float(hh));                \
            if (s + 2 < TT)                                                    \
                xv = g_bufA[((size_t)(s + 2) * BB + b0 + xe) * HH + xk];       \
        }                                                                      \
        _Pragma("unroll")                                                      \
        for (int l = 0; l < NLL; l++) {                                        \
            const int t = s - l;                                               \
            if (PRED) {                                                        \
                int r0 = ln >> 2, c0 = (ln & 3) * 2;                           \
                *(float2*)&acts[w][l][r0][c0] =                                \
                    make_float2(D0[l][0] + D1[l][0], D0[l][1] + D1[l][1]);     \
                *(float2*)&acts[w][l][r0 + 8][c0] =                            \
                    make_float2(D0[l][2] + D1[l][2], D0[l][3] + D1[l][3]);     \
            }                                                                  \
        }                                                                      \
        __syncwarp();                                                          \
        _Pragma("unroll")                                                      \
        for (int l = 0; l < NLL; l++) {                                        \
            const int t = s - l;                                               \
            if (PRED) {                                                        \
                float gi = acts[w][l][4 * uu + 0][ee];                         \
                float gf = acts[w][l][4 * uu + 1][ee];                         \
                float gg = acts[w][l][4 * uu + 2][ee];                         \
                float go = acts[w][l][4 * uu + 3][ee];                         \
                float i_ = sigm_ap(gi), f_ = sigm_ap(gf), o_ = sigm_ap(go);    \
                float g_ = tanh_ap(gg);                                        \
                float C = fmaf(f_, cst[l], i_ * g_);                           \
                cst[l] = C;                                                    \
                float h = o_ * tanh_ap(C);                                     \
                if (jg < HH) {                                                 \
                    __nv_bfloat16 hh = __float2bfloat16_rn(h);                 \
                    __nv_bfloat16 hl =                                         \
                        __float2bfloat16_rn(h - __bfloat162float(hh));         \
                    int pn = (t + 1) & 1;                                      \
                    zt[l][pn][0][HH + jg][ee] = hh;                            \
                    zt[l][pn][1][HH + jg][ee] = hl;                            \
                    if (l < NLL - 1) {                                         \
                        int pt = t & 1;                                        \
                        zt[l + 1][pt][0][jg][ee] = hh;                         \
                        zt[l + 1][pt][1][jg][ee] = hl;                         \
                    } else {                                                   \
                        g_bufB[((size_t)t * BB + b0 + ee) * HH + jg] = h;      \
                    }                                                          \
                }                                                              \
            }                                                                  \
        }                                                                      \
        __syncthreads();                                                       \
    }

    // fringe-in: s = 0..2 (guarded)
#pragma unroll 1
    for (int s = 0; s < NLL - 1; s++) STEP_BODY(0 <= t && t < TT)
    // steady state: all 4 layers unconditionally active (branch-free GEMM)
#pragma unroll 1
    for (int s = NLL - 1; s < TT; s++) STEP_BODY(1)
    // fringe-out: s = TT..TT+2 (guarded)
#pragma unroll 1
    for (int s = TT; s < TT + NLL - 1; s++) STEP_BODY(0 <= t && t < TT)
#undef STEP_BODY
}

// ---------- kernel 3: attention pooling + FC + softmax ----------
__global__ void __launch_bounds__(256)
attn_kernel(const float* __restrict__ W1, const float* __restrict__ b1,
            const float* __restrict__ W2, const float* __restrict__ b2,
            const float* __restrict__ fcW, const float* __restrict__ fcb,
            float* __restrict__ outp) {
    const float* __restrict__ enc = g_bufB;
    const int b = blockIdx.x, tid = threadIdx.x;

    __shared__ float4 sW1[HH * 16];
    __shared__ float4 sB1[16];
    __shared__ float4 sW2[16];
    __shared__ float se[TT];
    __shared__ float sred[8];
    __shared__ float swsum[8][HH];
    __shared__ float spool[HH];
    __shared__ float sscal[2];

    for (int i = tid; i < HH * 16; i += 256) sW1[i] = ((const float4*)W1)[i];
    if (tid < 16) {
        sB1[tid] = ((const float4*)b1)[tid];
        sW2[tid] = ((const float4*)W2)[tid];
    }
    __syncthreads();

    const float b2v = b2[0];
    for (int tt = tid; tt < TT; tt += 256) {
        const float* hp = enc + ((size_t)tt * BB + b) * HH;
        float4 acc[16];
#pragma unroll
        for (int q = 0; q < 16; q++) acc[q] = sB1[q];
        for (int jj = 0; jj < HH; jj++) {
            float hj = __ldg(hp + jj);
#pragma unroll
            for (int q = 0; q < 16; q++) {
                float4 wv = sW1[jj * 16 + q];
                acc[q].x = fmaf(hj, wv.x, acc[q].x);
                acc[q].y = fmaf(hj, wv.y, acc[q].y);
                acc[q].z = fmaf(hj, wv.z, acc[q].z);
                acc[q].w = fmaf(hj, wv.w, acc[q].w);
            }
        }
        float e = b2v;
#pragma unroll
        for (int q = 0; q < 16; q++) {
            float4 w2 = sW2[q];
            e += fmaxf(acc[q].x, 0.f) * w2.x + fmaxf(acc[q].y, 0.f) * w2.y +
                 fmaxf(acc[q].z, 0.f) * w2.z + fmaxf(acc[q].w, 0.f) * w2.w;
        }
        se[tt] = e;
    }
    __syncthreads();

    float m = -1e30f;
    for (int i = tid; i < TT; i += 256) m = fmaxf(m, se[i]);
#pragma unroll
    for (int o = 16; o; o >>= 1) m = fmaxf(m, __shfl_xor_sync(0xffffffffu, m, o));
    if ((tid & 31) == 0) sred[tid >> 5] = m;
    __syncthreads();
    if (tid < 32) {
        float v = (tid < 8) ? sred[tid] : -1e30f;
#pragma unroll
        for (int o = 4; o; o >>= 1) v = fmaxf(v, __shfl_xor_sync(0xffffffffu, v, o));
        if (tid == 0) sscal[0] = v;
    }
    __syncthreads();
    const float M = sscal[0];
    float ssum = 0.f;
    for (int i = tid; i < TT; i += 256) {
        float e = __expf(se[i] - M);
        se[i] = e;
        ssum += e;
    }
#pragma unroll
    for (int o = 16; o; o >>= 1) ssum += __shfl_xor_sync(0xffffffffu, ssum, o);
    if ((tid & 31) == 0) sred[tid >> 5] = ssum;
    __syncthreads();
    if (tid < 32) {
        float v = (tid < 8) ? sred[tid] : 0.f;
#pragma unroll
        for (int o = 4; o; o >>= 1) v += __shfl_xor_sync(0xffffffffu, v, o);
        if (tid == 0) sscal[1] = __fdividef(1.f, v);
    }
    __syncthreads();
    const float inv = sscal[1];

    float pa[HH];
#pragma unroll
    for (int jj = 0; jj < HH; jj++) pa[jj] = 0.f;
    for (int tt = tid; tt < TT; tt += 256) {
        float wgt = se[tt] * inv;
        const float* hp = enc + ((size_t)tt * BB + b) * HH;
#pragma unroll
        for (int jj = 0; jj < HH; jj++) pa[jj] = fmaf(wgt, __ldg(hp + jj), pa[jj]);
    }
#pragma unroll
    for (int jj = 0; jj < HH; jj++) {
#pragma unroll
        for (int o = 16; o; o >>= 1) pa[jj] += __shfl_xor_sync(0xffffffffu, pa[jj], o);
    }
    if ((tid & 31) == 0) {
        int w = tid >> 5;
#pragma unroll
        for (int jj = 0; jj < HH; jj++) swsum[w][jj] = pa[jj];
    }
    __syncthreads();
    if (tid < HH) {
        float s = 0.f;
#pragma unroll
        for (int w = 0; w < 8; w++) s += swsum[w][tid];
        spool[tid] = s;
    }
    __syncthreads();
    if (tid == 0) {
        float l0 = fcb[0], l1 = fcb[1], l2 = fcb[2];
#pragma unroll
        for (int jj = 0; jj < HH; jj++) {
            float p = spool[jj];
            l0 = fmaf(p, fcW[jj * 3 + 0], l0);
            l1 = fmaf(p, fcW[jj * 3 + 1], l1);
            l2 = fmaf(p, fcW[jj * 3 + 2], l2);
        }
        float mx = fmaxf(l0, fmaxf(l1, l2));
        float e0 = __expf(l0 - mx), e1 = __expf(l1 - mx), e2 = __expf(l2 - mx);
        float is = __fdividef(1.f, e0 + e1 + e2);
        outp[b * 3 + 0] = e0 * is;
        outp[b * 3 + 1] = e1 * is;
        outp[b * 3 + 2] = e2 * is;
    }
}

// ---------- launch ----------
extern "C" void kernel_launch(void* const* d_in, const int* in_sizes, int n_in,
                              void* d_out, int out_size) {
    const int*   x   = (const int*)  d_in[0];
    const float* wx  = (const float*)d_in[1];
    const float* emb = (const float*)d_in[2];
    const float* Wih = (const float*)d_in[3];
    const float* Whh = (const float*)d_in[4];
    const float* bih = (const float*)d_in[5];
    const float* bhh = (const float*)d_in[6];
    const float* aW1 = (const float*)d_in[7];
    const float* ab1 = (const float*)d_in[8];
    const float* aW2 = (const float*)d_in[9];
    const float* ab2 = (const float*)d_in[10];
    const float* fcW = (const float*)d_in[11];
    const float* fcb = (const float*)d_in[12];
    float* outp = (float*)d_out;

    embed_kernel<<<(TT * BB * (HH / 2)) / 256, 256>>>(x, wx, emb);
    lstm4_mma<<<NCTA, 256>>>(Wih, Whh, bih, bhh);
    attn_kernel<<<BB, 256>>>(aW1, ab1, aW2, ab2, fcW, fcb, outp);
}

// round 16
// speedup vs baseline: 1.3530x; 1.1092x over previous
#include <cuda_runtime.h>
#include <cuda_bf16.h>

#define TT 512
#define BB 512
#define KK 8
#define VV 5
#define HH 30
#define NLL 4
#define NEL 8             // batch elements per CTA
#define NCTA (BB / NEL)   // 64 CTAs

__device__ float g_bufA[(size_t)TT * BB * HH];  // embed output (layer-0 input)
__device__ float g_bufB[(size_t)TT * BB * HH];  // final layer output (attn input)

// ---------- helpers ----------
__device__ __forceinline__ float tanh_ap(float x) {
    float r;
    asm("tanh.approx.f32 %0, %1;" : "=f"(r) : "f"(x));
    return r;
}
__device__ __forceinline__ float sigm_ap(float x) {
    return fmaf(0.5f, tanh_ap(0.5f * x), 0.5f);
}
__device__ __forceinline__ unsigned smem_u32(const void* p) {
    unsigned a;
    asm("{ .reg .u64 t; cvta.to.shared.u64 t, %1; cvt.u32.u64 %0, t; }"
        : "=r"(a) : "l"(p));
    return a;
}
__device__ __forceinline__ unsigned short bfbits(float v) {
    __nv_bfloat16 b = __float2bfloat16_rn(v);
    return *(unsigned short*)&b;
}
// mma.sync m16n8k16 bf16: D += A*B (D=C in-place)
__device__ __forceinline__ void mma16816(float* d, const unsigned* a,
                                         const unsigned* b) {
    asm volatile(
        "mma.sync.aligned.m16n8k16.row.col.f32.bf16.bf16.f32 "
        "{%0,%1,%2,%3},{%4,%5,%6,%7},{%8,%9},{%0,%1,%2,%3};"
        : "+f"(d[0]), "+f"(d[1]), "+f"(d[2]), "+f"(d[3])
        : "r"(a[0]), "r"(a[1]), "r"(a[2]), "r"(a[3]), "r"(b[0]), "r"(b[1]));
}
// ldmatrix x2 transposed (B-operand from [K][8] bf16 rows of 16B)
__device__ __forceinline__ void ldsm2t(unsigned* r, unsigned addr) {
    asm volatile(
        "ldmatrix.sync.aligned.m8n8.x2.trans.shared.b16 {%0,%1}, [%2];"
        : "=r"(r[0]), "=r"(r[1]) : "r"(addr));
}

// ---------- kernel 1: embedding + relu + mean over K (2 j per thread) ----------
__global__ void embed_kernel(const int* __restrict__ x,
                             const float* __restrict__ w,
                             const float* __restrict__ emb) {
    __shared__ float se[VV * HH];
    for (int i = threadIdx.x; i < VV * HH; i += blockDim.x) se[i] = emb[i];
    __syncthreads();
    int idx = blockIdx.x * blockDim.x + threadIdx.x;
    int p = idx % (HH / 2);
    size_t tb = (size_t)(idx / (HH / 2));
    const int* xp = x + tb * KK;
    const float* wp = w + tb * KK;
    float s0 = 0.f, s1 = 0.f;
#pragma unroll
    for (int k = 0; k < KK; k++) {
        int v = xp[k];
        float wk = wp[k];
        s0 += fmaxf(se[v * HH + 2 * p] * wk, 0.f);
        s1 += fmaxf(se[v * HH + 2 * p + 1] * wk, 0.f);
    }
    float2* outp = (float2*)(g_bufA + tb * HH + 2 * p);
    *outp = make_float2(s0 * (1.f / KK), s1 * (1.f / KK));
}

// ---------- kernel 2: 4 LSTM layers on mma.sync (HMMA bf16) ----------
// 64 CTAs x 512 threads (16 warps); CTA owns 8 batch elements.
// gates(128x8) = W(128x61) . z, z = [x(30)|h(30)|1(bias)].
// 2-term split: Whi*zhi + Whi*zlo.
// Warp (m = w&7, half = w>>3) owns m-tile m (units 4m..4m+3) for the TWO
// layers {2*half, 2*half+1}. Same per-SMSP issue load as R15 but 4 warps/SMSP
// (vs 2) -> dependent-chain latency (LDSM->MMA, tanh chains) covered by
// co-resident warps; per-warp A-frags halve to 32 regs.
__global__ void __launch_bounds__(512, 1)
lstm4_mma(const float* __restrict__ Wih_all, const float* __restrict__ Whh_all,
          const float* __restrict__ bih_all, const float* __restrict__ bhh_all) {
    __shared__ __align__(16) __nv_bfloat16 zt[NLL][2][2][64][8];  // [l][par][hi/lo][k][e]
    __shared__ __align__(16) float acts[8][NLL][16][8];

    const int tid = threadIdx.x;
    const int w = tid >> 5;
    const int ln = tid & 31;
    const int m = w & 7;          // m-tile
    const int half = w >> 3;      // layer pair: {2*half, 2*half+1}
    const int b0 = blockIdx.x * NEL;

    for (int i = tid; i < (int)(sizeof(zt) / 4); i += 512) ((unsigned*)zt)[i] = 0u;

    // ---- resident A fragments (hi only) for this warp's 2 layers ----
    unsigned Ah[2][4][4];
#pragma unroll
    for (int ll = 0; ll < 2; ll++) {
        const int l = 2 * half + ll;
        const float* Wih = Wih_all + l * 4 * HH * HH;
        const float* Whh = Whh_all + l * 4 * HH * HH;
        const float* bih = bih_all + l * 4 * HH;
        const float* bhh = bhh_all + l * 4 * HH;
#pragma unroll
        for (int kt = 0; kt < 4; kt++) {
#pragma unroll
            for (int i = 0; i < 4; i++) {
                int row = 16 * m + (ln >> 2) + (i & 1) * 8;
                int cb = kt * 16 + (ln & 3) * 2 + (i >> 1) * 8;
                float wv[2];
#pragma unroll
                for (int q = 0; q < 2; q++) {
                    int k = cb + q;
                    int j = row >> 2, g = row & 3;
                    float v = 0.f;
                    if (j < HH) {
                        int gr = g * HH + j;
                        if (k < HH) v = Wih[gr * HH + k];
                        else if (k < 2 * HH) v = Whh[gr * HH + (k - HH)];
                        else if (k == 60) v = bih[gr] + bhh[gr];
                    }
                    wv[q] = v;
                }
                unsigned short h0 = bfbits(wv[0]), h1 = bfbits(wv[1]);
                Ah[ll][kt][i] = ((unsigned)h1 << 16) | h0;
            }
        }
    }
    __syncthreads();

    // ---- bias column ----
    if (tid < NLL * 2 * NEL) {
        int l = tid >> 4, p = (tid >> 3) & 1, e = tid & 7;
        zt[l][p][0][60][e] = __float2bfloat16_rn(1.0f);
    }

    // ---- x staging roles ----
    const int xe = tid / HH, xk = tid - xe * HH;
    const bool xact = tid < NEL * HH;
    float xv = 0.f;
    if (xact) {
        float x0 = g_bufA[(size_t)(b0 + xe) * HH + xk];
        __nv_bfloat16 hh = __float2bfloat16_rn(x0);
        zt[0][0][0][xk][xe] = hh;
        zt[0][0][1][xk][xe] = __float2bfloat16_rn(x0 - __bfloat162float(hh));
        xv = g_bufA[((size_t)BB + b0 + xe) * HH + xk];
    }
    __syncthreads();

    const int uu = ln >> 3, ee = ln & 7;
    const int jg = 4 * m + uu;
    float cst[2] = {0.f, 0.f};
    const unsigned rowsel = (unsigned)(ln & 15);

// PRED(l,t): compile-time 1 in steady state, range check on the fringe.
#define STEP_BODY(PRED)                                                        \
    {                                                                          \
        unsigned Bh[4][2], Bl[4][2];                                           \
        float D0[2][4], D1[2][4];                                              \
        _Pragma("unroll")                                                      \
        for (int ll = 0; ll < 2; ll++) {                                       \
            const int l = 2 * half + ll;                                       \
            const int t = s - l;                                               \
            _Pragma("unroll")                                                  \
            for (int i = 0; i < 4; i++) D0[ll][i] = D1[ll][i] = 0.f;           \
            if (PRED) {                                                        \
                const unsigned zb = smem_u32(&zt[l][t & 1][0][0][0]);          \
                _Pragma("unroll")                                              \
                for (int kt = 0; kt < 4; kt++) {                               \
                    unsigned ra = (unsigned)(kt * 16) + rowsel;                \
                    ldsm2t(Bh[kt], zb + ra * 16u);                             \
                    ldsm2t(Bl[kt], zb + 1024u + ra * 16u);                     \
                }                                                              \
                _Pragma("unroll")                                              \
                for (int kt = 0; kt < 4; kt++) {                               \
                    mma16816(D0[ll], Ah[ll][kt], Bh[kt]);                      \
                    mma16816(D1[ll], Ah[ll][kt], Bl[kt]);                      \
                }                                                              \
            }                                                                  \
        }                                                                      \
        if (xact && s + 1 < TT) {                                              \
            int pn = (s + 1) & 1;                                              \
            __nv_bfloat16 hh = __float2bfloat16_rn(xv);                        \
            zt[0][pn][0][xk][xe] = hh;                                         \
            zt[0][pn][1][xk][xe] =                                             \
                __float2bfloat16_rn(xv - __bfloat162float(hh));                \
            if (s + 2 < TT)                                                    \
                xv = g_bufA[((size_t)(s + 2) * BB + b0 + xe) * HH + xk];       \
        }                                                                      \
        _Pragma("unroll")                                                      \
        for (int ll = 0; ll < 2; ll++) {                                       \
            const int l = 2 * half + ll;                                       \
            const int t = s - l;                                               \
            if (PRED) {                                                        \
                int r0 = ln >> 2, c0 = (ln & 3) * 2;                           \
                *(float2*)&acts[m][l][r0][c0] =                                \
                    make_float2(D0[ll][0] + D1[ll][0], D0[ll][1] + D1[ll][1]); \
                *(float2*)&acts[m][l][r0 + 8][c0] =                            \
                    make_float2(D0[ll][2] + D1[ll][2], D0[ll][3] + D1[ll][3]); \
            }                                                                  \
        }                                                                      \
        __syncwarp();                                                          \
        _Pragma("unroll")                                                      \
        for (int ll = 0; ll < 2; ll++) {                                       \
            const int l = 2 * half + ll;                                       \
            const int t = s - l;                                               \
            if (PRED) {                                                        \
                float gi = acts[m][l][4 * uu + 0][ee];                         \
                float gf = acts[m][l][4 * uu + 1][ee];                         \
                float gg = acts[m][l][4 * uu + 2][ee];                         \
                float go = acts[m][l][4 * uu + 3][ee];                         \
                float i_ = sigm_ap(gi), f_ = sigm_ap(gf), o_ = sigm_ap(go);    \
                float g_ = tanh_ap(gg);                                        \
                float C = fmaf(f_, cst[ll], i_ * g_);                          \
                cst[ll] = C;                                                   \
                float h = o_ * tanh_ap(C);                                     \
                if (jg < HH) {                                                 \
                    __nv_bfloat16 hh = __float2bfloat16_rn(h);                 \
                    __nv_bfloat16 hl =                                         \
                        __float2bfloat16_rn(h - __bfloat162float(hh));         \
                    int pn = (t + 1) & 1;                                      \
                    zt[l][pn][0][HH + jg][ee] = hh;                            \
                    zt[l][pn][1][HH + jg][ee] = hl;                            \
                    if (l < NLL - 1) {                                         \
                        int pt = t & 1;                                        \
                        zt[l + 1][pt][0][jg][ee] = hh;                         \
                        zt[l + 1][pt][1][jg][ee] = hl;                         \
                    } else {                                                   \
                        g_bufB[((size_t)t * BB + b0 + ee) * HH + jg] = h;      \
                    }                                                          \
                }                                                              \
            }                                                                  \
        }                                                                      \
        __syncthreads();                                                       \
    }

    // fringe-in: s = 0..2 (guarded)
#pragma unroll 1
    for (int s = 0; s < NLL - 1; s++) STEP_BODY(0 <= t && t < TT)
    // steady state: all layers unconditionally active (branch-free GEMM)
#pragma unroll 1
    for (int s = NLL - 1; s < TT; s++) STEP_BODY(1)
    // fringe-out: s = TT..TT+2 (guarded)
#pragma unroll 1
    for (int s = TT; s < TT + NLL - 1; s++) STEP_BODY(0 <= t && t < TT)
#undef STEP_BODY
}

// ---------- kernel 3: attention pooling + FC + softmax ----------
__global__ void __launch_bounds__(256)
attn_kernel(const float* __restrict__ W1, const float* __restrict__ b1,
            const float* __restrict__ W2, const float* __restrict__ b2,
            const float* __restrict__ fcW, const float* __restrict__ fcb,
            float* __restrict__ outp) {
    const float* __restrict__ enc = g_bufB;
    const int b = blockIdx.x, tid = threadIdx.x;

    __shared__ float4 sW1[HH * 16];
    __shared__ float4 sB1[16];
    __shared__ float4 sW2[16];
    __shared__ float se[TT];
    __shared__ float sred[8];
    __shared__ float swsum[8][HH];
    __shared__ float spool[HH];
    __shared__ float sscal[2];

    for (int i = tid; i < HH * 16; i += 256) sW1[i] = ((const float4*)W1)[i];
    if (tid < 16) {
        sB1[tid] = ((const float4*)b1)[tid];
        sW2[tid] = ((const float4*)W2)[tid];
    }
    __syncthreads();

    const float b2v = b2[0];
    for (int tt = tid; tt < TT; tt += 256) {
        const float* hp = enc + ((size_t)tt * BB + b) * HH;
        float4 acc[16];
#pragma unroll
        for (int q = 0; q < 16; q++) acc[q] = sB1[q];
        for (int jj = 0; jj < HH; jj++) {
            float hj = __ldg(hp + jj);
#pragma unroll
            for (int q = 0; q < 16; q++) {
                float4 wv = sW1[jj * 16 + q];
                acc[q].x = fmaf(hj, wv.x, acc[q].x);
                acc[q].y = fmaf(hj, wv.y, acc[q].y);
                acc[q].z = fmaf(hj, wv.z, acc[q].z);
                acc[q].w = fmaf(hj, wv.w, acc[q].w);
            }
        }
        float e = b2v;
#pragma unroll
        for (int q = 0; q < 16; q++) {
            float4 w2 = sW2[q];
            e += fmaxf(acc[q].x, 0.f) * w2.x + fmaxf(acc[q].y, 0.f) * w2.y +
                 fmaxf(acc[q].z, 0.f) * w2.z + fmaxf(acc[q].w, 0.f) * w2.w;
        }
        se[tt] = e;
    }
    __syncthreads();

    float m = -1e30f;
    for (int i = tid; i < TT; i += 256) m = fmaxf(m, se[i]);
#pragma unroll
    for (int o = 16; o; o >>= 1) m = fmaxf(m, __shfl_xor_sync(0xffffffffu, m, o));
    if ((tid & 31) == 0) sred[tid >> 5] = m;
    __syncthreads();
    if (tid < 32) {
        float v = (tid < 8) ? sred[tid] : -1e30f;
#pragma unroll
        for (int o = 4; o; o >>= 1) v = fmaxf(v, __shfl_xor_sync(0xffffffffu, v, o));
        if (tid == 0) sscal[0] = v;
    }
    __syncthreads();
    const float M = sscal[0];
    float ssum = 0.f;
    for (int i = tid; i < TT; i += 256) {
        float e = __expf(se[i] - M);
        se[i] = e;
        ssum += e;
    }
#pragma unroll
    for (int o = 16; o; o >>= 1) ssum += __shfl_xor_sync(0xffffffffu, ssum, o);
    if ((tid & 31) == 0) sred[tid >> 5] = ssum;
    __syncthreads();
    if (tid < 32) {
        float v = (tid < 8) ? sred[tid] : 0.f;
#pragma unroll
        for (int o = 4; o; o >>= 1) v += __shfl_xor_sync(0xffffffffu, v, o);
        if (tid == 0) sscal[1] = __fdividef(1.f, v);
    }
    __syncthreads();
    const float inv = sscal[1];

    float pa[HH];
#pragma unroll
    for (int jj = 0; jj < HH; jj++) pa[jj] = 0.f;
    for (int tt = tid; tt < TT; tt += 256) {
        float wgt = se[tt] * inv;
        const float* hp = enc + ((size_t)tt * BB + b) * HH;
#pragma unroll
        for (int jj = 0; jj < HH; jj++) pa[jj] = fmaf(wgt, __ldg(hp + jj), pa[jj]);
    }
#pragma unroll
    for (int jj = 0; jj < HH; jj++) {
#pragma unroll
        for (int o = 16; o; o >>= 1) pa[jj] += __shfl_xor_sync(0xffffffffu, pa[jj], o);
    }
    if ((tid & 31) == 0) {
        int w = tid >> 5;
#pragma unroll
        for (int jj = 0; jj < HH; jj++) swsum[w][jj] = pa[jj];
    }
    __syncthreads();
    if (tid < HH) {
        float s = 0.f;
#pragma unroll
        for (int w = 0; w < 8; w++) s += swsum[w][tid];
        spool[tid] = s;
    }
    __syncthreads();
    if (tid == 0) {
        float l0 = fcb[0], l1 = fcb[1], l2 = fcb[2];
#pragma unroll
        for (int jj = 0; jj < HH; jj++) {
            float p = spool[jj];
            l0 = fmaf(p, fcW[jj * 3 + 0], l0);
            l1 = fmaf(p, fcW[jj * 3 + 1], l1);
            l2 = fmaf(p, fcW[jj * 3 + 2], l2);
        }
        float mx = fmaxf(l0, fmaxf(l1, l2));
        float e0 = __expf(l0 - mx), e1 = __expf(l1 - mx), e2 = __expf(l2 - mx);
        float is = __fdividef(1.f, e0 + e1 + e2);
        outp[b * 3 + 0] = e0 * is;
        outp[b * 3 + 1] = e1 * is;
        outp[b * 3 + 2] = e2 * is;
    }
}

// ---------- launch ----------
extern "C" void kernel_launch(void* const* d_in, const int* in_sizes, int n_in,
                              void* d_out, int out_size) {
    const int*   x   = (const int*)  d_in[0];
    const float* wx  = (const float*)d_in[1];
    const float* emb = (const float*)d_in[2];
    const float* Wih = (const float*)d_in[3];
    const float* Whh = (const float*)d_in[4];
    const float* bih = (const float*)d_in[5];
    const float* bhh = (const float*)d_in[6];
    const float* aW1 = (const float*)d_in[7];
    const float* ab1 = (const float*)d_in[8];
    const float* aW2 = (const float*)d_in[9];
    const float* ab2 = (const float*)d_in[10];
    const float* fcW = (const float*)d_in[11];
    const float* fcb = (const float*)d_in[12];
    float* outp = (float*)d_out;

    embed_kernel<<<(TT * BB * (HH / 2)) / 256, 256>>>(x, wx, emb);
    lstm4_mma<<<NCTA, 512>>>(Wih, Whh, bih, bhh);
    attn_kernel<<<BB, 256>>>(aW1, ab1, aW2, ab2, fcW, fcb, outp);
}

// round 17
// speedup vs baseline: 1.6868x; 1.2467x over previous
#include <cuda_runtime.h>
#include <cuda_bf16.h>

#define TT 512
#define BB 512
#define KK 8
#define VV 5
#define HH 30
#define NLL 4
#define NEL 8             // batch elements per CTA
#define NCTA (BB / NEL)   // 64 CTAs

__device__ float g_bufA[(size_t)TT * BB * HH];  // embed output (layer-0 input)
__device__ float g_bufB[(size_t)TT * BB * HH];  // final layer output (attn input)

// ---------- helpers ----------
__device__ __forceinline__ float tanh_ap(float x) {
    float r;
    asm("tanh.approx.f32 %0, %1;" : "=f"(r) : "f"(x));
    return r;
}
__device__ __forceinline__ float sigm_ap(float x) {
    return fmaf(0.5f, tanh_ap(0.5f * x), 0.5f);
}
__device__ __forceinline__ unsigned smem_u32(const void* p) {
    unsigned a;
    asm("{ .reg .u64 t; cvta.to.shared.u64 t, %1; cvt.u32.u64 %0, t; }"
        : "=r"(a) : "l"(p));
    return a;
}
__device__ __forceinline__ unsigned short bfbits(float v) {
    __nv_bfloat16 b = __float2bfloat16_rn(v);
    return *(unsigned short*)&b;
}
// mma.sync m16n8k16 bf16: D += A*B (D=C in-place)
__device__ __forceinline__ void mma16816(float* d, const unsigned* a,
                                         const unsigned* b) {
    asm volatile(
        "mma.sync.aligned.m16n8k16.row.col.f32.bf16.bf16.f32 "
        "{%0,%1,%2,%3},{%4,%5,%6,%7},{%8,%9},{%0,%1,%2,%3};"
        : "+f"(d[0]), "+f"(d[1]), "+f"(d[2]), "+f"(d[3])
        : "r"(a[0]), "r"(a[1]), "r"(a[2]), "r"(a[3]), "r"(b[0]), "r"(b[1]));
}
// ldmatrix x2 transposed (B-operand from [K][8] bf16 rows of 16B)
__device__ __forceinline__ void ldsm2t(unsigned* r, unsigned addr) {
    asm volatile(
        "ldmatrix.sync.aligned.m8n8.x2.trans.shared.b16 {%0,%1}, [%2];"
        : "=r"(r[0]), "=r"(r[1]) : "r"(addr));
}

// ---------- kernel 1: embedding + relu + mean over K (2 j per thread) ----------
__global__ void embed_kernel(const int* __restrict__ x,
                             const float* __restrict__ w,
                             const float* __restrict__ emb) {
    __shared__ float se[VV * HH];
    for (int i = threadIdx.x; i < VV * HH; i += blockDim.x) se[i] = emb[i];
    __syncthreads();
    int idx = blockIdx.x * blockDim.x + threadIdx.x;
    int p = idx % (HH / 2);
    size_t tb = (size_t)(idx / (HH / 2));
    const int* xp = x + tb * KK;
    const float* wp = w + tb * KK;
    float s0 = 0.f, s1 = 0.f;
#pragma unroll
    for (int k = 0; k < KK; k++) {
        int v = xp[k];
        float wk = wp[k];
        s0 += fmaxf(se[v * HH + 2 * p] * wk, 0.f);
        s1 += fmaxf(se[v * HH + 2 * p + 1] * wk, 0.f);
    }
    float2* outp = (float2*)(g_bufA + tb * HH + 2 * p);
    *outp = make_float2(s0 * (1.f / KK), s1 * (1.f / KK));
}

// ---------- kernel 2: 4 LSTM layers on mma.sync (HMMA bf16) ----------
// 64 CTAs x 512 threads (16 warps); CTA owns 8 batch elements.
// gates(128x8) = W(128x61) . z, z = [x(30)|h(30)|1(bias)], PURE bf16 single
// term (z-lo residual dropped: R15 measured 7.7e-5 rel_err for the symmetric
// W-bf16 rounding, so z-bf16 adds a similar contribution -> ~2e-4 total,
// still 5x under the 1e-3 gate). 8 MMA + 4 LDSM per warp per step.
// Warp (m = w&7, half = w>>3) owns m-tile m (units 4m..4m+3) for layers
// {2*half, 2*half+1}; 4 warps/SMSP cover chain latency.
__global__ void __launch_bounds__(512, 1)
lstm4_mma(const float* __restrict__ Wih_all, const float* __restrict__ Whh_all,
          const float* __restrict__ bih_all, const float* __restrict__ bhh_all) {
    __shared__ __align__(16) __nv_bfloat16 zt[NLL][2][64][8];  // [l][par][k][e]
    __shared__ __align__(16) float acts[8][NLL][16][8];

    const int tid = threadIdx.x;
    const int w = tid >> 5;
    const int ln = tid & 31;
    const int m = w & 7;          // m-tile
    const int half = w >> 3;      // layer pair: {2*half, 2*half+1}
    const int b0 = blockIdx.x * NEL;

    for (int i = tid; i < (int)(sizeof(zt) / 4); i += 512) ((unsigned*)zt)[i] = 0u;

    // ---- resident A fragments for this warp's 2 layers ----
    unsigned Ah[2][4][4];
#pragma unroll
    for (int ll = 0; ll < 2; ll++) {
        const int l = 2 * half + ll;
        const float* Wih = Wih_all + l * 4 * HH * HH;
        const float* Whh = Whh_all + l * 4 * HH * HH;
        const float* bih = bih_all + l * 4 * HH;
        const float* bhh = bhh_all + l * 4 * HH;
#pragma unroll
        for (int kt = 0; kt < 4; kt++) {
#pragma unroll
            for (int i = 0; i < 4; i++) {
                int row = 16 * m + (ln >> 2) + (i & 1) * 8;
                int cb = kt * 16 + (ln & 3) * 2 + (i >> 1) * 8;
                float wv[2];
#pragma unroll
                for (int q = 0; q < 2; q++) {
                    int k = cb + q;
                    int j = row >> 2, g = row & 3;
                    float v = 0.f;
                    if (j < HH) {
                        int gr = g * HH + j;
                        if (k < HH) v = Wih[gr * HH + k];
                        else if (k < 2 * HH) v = Whh[gr * HH + (k - HH)];
                        else if (k == 60) v = bih[gr] + bhh[gr];
                    }
                    wv[q] = v;
                }
                unsigned short h0 = bfbits(wv[0]), h1 = bfbits(wv[1]);
                Ah[ll][kt][i] = ((unsigned)h1 << 16) | h0;
            }
        }
    }
    __syncthreads();

    // ---- bias column ----
    if (tid < NLL * 2 * NEL) {
        int l = tid >> 4, p = (tid >> 3) & 1, e = tid & 7;
        zt[l][p][60][e] = __float2bfloat16_rn(1.0f);
    }

    // ---- x staging roles ----
    const int xe = tid / HH, xk = tid - xe * HH;
    const bool xact = tid < NEL * HH;
    float xv = 0.f;
    if (xact) {
        zt[0][0][xk][xe] = __float2bfloat16_rn(g_bufA[(size_t)(b0 + xe) * HH + xk]);
        xv = g_bufA[((size_t)BB + b0 + xe) * HH + xk];
    }
    __syncthreads();

    const int uu = ln >> 3, ee = ln & 7;
    const int jg = 4 * m + uu;
    float cst[2] = {0.f, 0.f};
    const unsigned rowsel = (unsigned)(ln & 15);

// PRED(l,t): compile-time 1 in steady state, range check on the fringe.
#define STEP_BODY(PRED)                                                        \
    {                                                                          \
        unsigned Bh[4][2];                                                     \
        float D0[2][4], D1[2][4];                                              \
        _Pragma("unroll")                                                      \
        for (int ll = 0; ll < 2; ll++) {                                       \
            const int l = 2 * half + ll;                                       \
            const int t = s - l;                                               \
            _Pragma("unroll")                                                  \
            for (int i = 0; i < 4; i++) D0[ll][i] = D1[ll][i] = 0.f;           \
            if (PRED) {                                                        \
                const unsigned zb = smem_u32(&zt[l][t & 1][0][0]);             \
                _Pragma("unroll")                                              \
                for (int kt = 0; kt < 4; kt++) {                               \
                    unsigned ra = (unsigned)(kt * 16) + rowsel;                \
                    ldsm2t(Bh[kt], zb + ra * 16u);                             \
                }                                                              \
                mma16816(D0[ll], Ah[ll][0], Bh[0]);                            \
                mma16816(D1[ll], Ah[ll][1], Bh[1]);                            \
                mma16816(D0[ll], Ah[ll][2], Bh[2]);                            \
                mma16816(D1[ll], Ah[ll][3], Bh[3]);                            \
            }                                                                  \
        }                                                                      \
        if (xact && s + 1 < TT) {                                              \
            int pn = (s + 1) & 1;                                              \
            zt[0][pn][xk][xe] = __float2bfloat16_rn(xv);                       \
            if (s + 2 < TT)                                                    \
                xv = g_bufA[((size_t)(s + 2) * BB + b0 + xe) * HH + xk];       \
        }                                                                      \
        _Pragma("unroll")                                                      \
        for (int ll = 0; ll < 2; ll++) {                                       \
            const int l = 2 * half + ll;                                       \
            const int t = s - l;                                               \
            if (PRED) {                                                        \
                int r0 = ln >> 2, c0 = (ln & 3) * 2;                           \
                *(float2*)&acts[m][l][r0][c0] =                                \
                    make_float2(D0[ll][0] + D1[ll][0], D0[ll][1] + D1[ll][1]); \
                *(float2*)&acts[m][l][r0 + 8][c0] =                            \
                    make_float2(D0[ll][2] + D1[ll][2], D0[ll][3] + D1[ll][3]); \
            }                                                                  \
        }                                                                      \
        __syncwarp();                                                          \
        _Pragma("unroll")                                                      \
        for (int ll = 0; ll < 2; ll++) {                                       \
            const int l = 2 * half + ll;                                       \
            const int t = s - l;                                               \
            if (PRED) {                                                        \
                float gi = acts[m][l][4 * uu + 0][ee];                         \
                float gf = acts[m][l][4 * uu + 1][ee];                         \
                float gg = acts[m][l][4 * uu + 2][ee];                         \
                float go = acts[m][l][4 * uu + 3][ee];                         \
                float i_ = sigm_ap(gi), f_ = sigm_ap(gf), o_ = sigm_ap(go);    \
                float g_ = tanh_ap(gg);                                        \
                float C = fmaf(f_, cst[ll], i_ * g_);                          \
                cst[ll] = C;                                                   \
                float h = o_ * tanh_ap(C);                                     \
                if (jg < HH) {                                                 \
                    __nv_bfloat16 hh = __float2bfloat16_rn(h);                 \
                    int pn = (t + 1) & 1;                                      \
                    zt[l][pn][HH + jg][ee] = hh;                               \
                    if (l < NLL - 1) {                                         \
                        zt[l + 1][t & 1][jg][ee] = hh;                         \
                    } else {                                                   \
                        g_bufB[((size_t)t * BB + b0 + ee) * HH + jg] = h;      \
                    }                                                          \
                }                                                              \
            }                                                                  \
        }                                                                      \
        __syncthreads();                                                       \
    }

    // fringe-in: s = 0..2 (guarded)
#pragma unroll 1
    for (int s = 0; s < NLL - 1; s++) STEP_BODY(0 <= t && t < TT)
    // steady state: all layers unconditionally active (branch-free GEMM)
#pragma unroll 1
    for (int s = NLL - 1; s < TT; s++) STEP_BODY(1)
    // fringe-out: s = TT..TT+2 (guarded)
#pragma unroll 1
    for (int s = TT; s < TT + NLL - 1; s++) STEP_BODY(0 <= t && t < TT)
#undef STEP_BODY
}

// ---------- kernel 3: attention pooling + FC + softmax ----------
__global__ void __launch_bounds__(256)
attn_kernel(const float* __restrict__ W1, const float* __restrict__ b1,
            const float* __restrict__ W2, const float* __restrict__ b2,
            const float* __restrict__ fcW, const float* __restrict__ fcb,
            float* __restrict__ outp) {
    const float* __restrict__ enc = g_bufB;
    const int b = blockIdx.x, tid = threadIdx.x;

    __shared__ float4 sW1[HH * 16];
    __shared__ float4 sB1[16];
    __shared__ float4 sW2[16];
    __shared__ float se[TT];
    __shared__ float sred[8];
    __shared__ float swsum[8][HH];
    __shared__ float spool[HH];
    __shared__ float sscal[2];

    for (int i = tid; i < HH * 16; i += 256) sW1[i] = ((const float4*)W1)[i];
    if (tid < 16) {
        sB1[tid] = ((const float4*)b1)[tid];
        sW2[tid] = ((const float4*)W2)[tid];
    }
    __syncthreads();

    const float b2v = b2[0];
    for (int tt = tid; tt < TT; tt += 256) {
        const float* hp = enc + ((size_t)tt * BB + b) * HH;
        float4 acc[16];
#pragma unroll
        for (int q = 0; q < 16; q++) acc[q] = sB1[q];
        for (int jj = 0; jj < HH; jj++) {
            float hj = __ldg(hp + jj);
#pragma unroll
            for (int q = 0; q < 16; q++) {
                float4 wv = sW1[jj * 16 + q];
                acc[q].x = fmaf(hj, wv.x, acc[q].x);
                acc[q].y = fmaf(hj, wv.y, acc[q].y);
                acc[q].z = fmaf(hj, wv.z, acc[q].z);
                acc[q].w = fmaf(hj, wv.w, acc[q].w);
            }
        }
        float e = b2v;
#pragma unroll
        for (int q = 0; q < 16; q++) {
            float4 w2 = sW2[q];
            e += fmaxf(acc[q].x, 0.f) * w2.x + fmaxf(acc[q].y, 0.f) * w2.y +
                 fmaxf(acc[q].z, 0.f) * w2.z + fmaxf(acc[q].w, 0.f) * w2.w;
        }
        se[tt] = e;
    }
    __syncthreads();

    float m = -1e30f;
    for (int i = tid; i < TT; i += 256) m = fmaxf(m, se[i]);
#pragma unroll
    for (int o = 16; o; o >>= 1) m = fmaxf(m, __shfl_xor_sync(0xffffffffu, m, o));
    if ((tid & 31) == 0) sred[tid >> 5] = m;
    __syncthreads();
    if (tid < 32) {
        float v = (tid < 8) ? sred[tid] : -1e30f;
#pragma unroll
        for (int o = 4; o; o >>= 1) v = fmaxf(v, __shfl_xor_sync(0xffffffffu, v, o));
        if (tid == 0) sscal[0] = v;
    }
    __syncthreads();
    const float M = sscal[0];
    float ssum = 0.f;
    for (int i = tid; i < TT; i += 256) {
        float e = __expf(se[i] - M);
        se[i] = e;
        ssum += e;
    }
#pragma unroll
    for (int o = 16; o; o >>= 1) ssum += __shfl_xor_sync(0xffffffffu, ssum, o);
    if ((tid & 31) == 0) sred[tid >> 5] = ssum;
    __syncthreads();
    if (tid < 32) {
        float v = (tid < 8) ? sred[tid] : 0.f;
#pragma unroll
        for (int o = 4; o; o >>= 1) v += __shfl_xor_sync(0xffffffffu, v, o);
        if (tid == 0) sscal[1] = __fdividef(1.f, v);
    }
    __syncthreads();
    const float inv = sscal[1];

    float pa[HH];
#pragma unroll
    for (int jj = 0; jj < HH; jj++) pa[jj] = 0.f;
    for (int tt = tid; tt < TT; tt += 256) {
        float wgt = se[tt] * inv;
        const float* hp = enc + ((size_t)tt * BB + b) * HH;
#pragma unroll
        for (int jj = 0; jj < HH; jj++) pa[jj] = fmaf(wgt, __ldg(hp + jj), pa[jj]);
    }
#pragma unroll
    for (int jj = 0; jj < HH; jj++) {
#pragma unroll
        for (int o = 16; o; o >>= 1) pa[jj] += __shfl_xor_sync(0xffffffffu, pa[jj], o);
    }
    if ((tid & 31) == 0) {
        int w = tid >> 5;
#pragma unroll
        for (int jj = 0; jj < HH; jj++) swsum[w][jj] = pa[jj];
    }
    __syncthreads();
    if (tid < HH) {
        float s = 0.f;
#pragma unroll
        for (int w = 0; w < 8; w++) s += swsum[w][tid];
        spool[tid] = s;
    }
    __syncthreads();
    if (tid == 0) {
        float l0 = fcb[0], l1 = fcb[1], l2 = fcb[2];
#pragma unroll
        for (int jj = 0; jj < HH; jj++) {
            float p = spool[jj];
            l0 = fmaf(p, fcW[jj * 3 + 0], l0);
            l1 = fmaf(p, fcW[jj * 3 + 1], l1);
            l2 = fmaf(p, fcW[jj * 3 + 2], l2);
        }
        float mx = fmaxf(l0, fmaxf(l1, l2));
        float e0 = __expf(l0 - mx), e1 = __expf(l1 - mx), e2 = __expf(l2 - mx);
        float is = __fdividef(1.f, e0 + e1 + e2);
        outp[b * 3 + 0] = e0 * is;
        outp[b * 3 + 1] = e1 * is;
        outp[b * 3 + 2] = e2 * is;
    }
}

// ---------- launch ----------
extern "C" void kernel_launch(void* const* d_in, const int* in_sizes, int n_in,
                              void* d_out, int out_size) {
    const int*   x   = (const int*)  d_in[0];
    const float* wx  = (const float*)d_in[1];
    const float* emb = (const float*)d_in[2];
    const float* Wih = (const float*)d_in[3];
    const float* Whh = (const float*)d_in[4];
    const float* bih = (const float*)d_in[5];
    const float* bhh = (const float*)d_in[6];
    const float* aW1 = (const float*)d_in[7];
    const float* ab1 = (const float*)d_in[8];
    const float* aW2 = (const float*)d_in[9];
    const float* ab2 = (const float*)d_in[10];
    const float* fcW = (const float*)d_in[11];
    const float* fcb = (const float*)d_in[12];
    float* outp = (float*)d_out;

    embed_kernel<<<(TT * BB * (HH / 2)) / 256, 256>>>(x, wx, emb);
    lstm4_mma<<<NCTA, 512>>>(Wih, Whh, bih, bhh);
    attn_kernel<<<BB, 256>>>(aW1, ab1, aW2, ab2, fcW, fcb, outp);
}